// round 6
// baseline (speedup 1.0000x reference)
#include <cuda_runtime.h>
#include <cuda_bf16.h>
#include <cstddef>

// ---------------------------------------------------------------------------
// pygGCN: 3-layer GCN, N=50000, E=200000, feats 512 -> 2048 -> 256 -> 64
//
// Algebraic restructure: A_norm @ (X @ W) == (A_norm @ X) @ W, aggregate on
// the narrow side of each layer:
//   L1: agg0 = A_norm @ X (512)      ; H1 = leaky_relu(agg0 @ W1 + b1)
//   L2: T2   = H1 @ W2 (256)         ; H2 = b2 + A_norm @ T2
//   L3: T3   = relu(H2) @ W3 (64)    ; oacc = b3 + A_norm @ T3 ; out = relu(oacc)
// Self-loops handled analytically (dinv[i]^2 term in agg-init).
// H1 (410 MB) never materialized: GEMM1->GEMM2 chunked 4 x 12500 rows.
//
// Robustness (root-cause fixes for rounds 1-5 failures):
//  * inputs identified by element count (order-proof) — all 9 sizes unique
//  * edge_index dtype (int32 vs int64) probed ON DEVICE (JAX silently
//    downcasts int64->int32 without x64 mode)
//  * all indices clamped to [0, NNODES) — garbage can't wild-write
//  * no atomics target harness memory; d_out gets plain stores only
//  * kernel_launch = kernel launches only, no CUDA API calls
// ---------------------------------------------------------------------------

#define NNODES 50000
#define NEDGES 200000
#define FF0 512
#define FF1 2048
#define FF2 256
#define FF3 64
#define CHUNK 12500
#define NCHUNKS (NNODES / CHUNK)

// Device scratch (static __device__ arrays; allocation-free). ~283 MB total.
__device__ int   g_is64;
__device__ float g_deg [NNODES];
__device__ float g_dinv[NNODES];
__device__ int   g_row [NEDGES];
__device__ int   g_col [NEDGES];
__device__ float g_w   [NEDGES];                 // dinv[r]*ew*dinv[c]
__device__ float g_agg0[(size_t)NNODES * FF0];   // 102 MB
__device__ float g_hc  [(size_t)CHUNK  * FF1];   // 102 MB (chunked H1)
__device__ float g_t2  [(size_t)NNODES * FF2];   //  51 MB
__device__ float g_h2  [(size_t)NNODES * FF2];   //  51 MB
__device__ float g_t3  [(size_t)NNODES * FF3];   //  13 MB
__device__ float g_oacc[(size_t)NNODES * FF3];   //  13 MB

// Compile-time scratch selector. SEL >= 0 -> device global; SEL == -1 -> arg.
#define SEL_ARG  (-1)
#define SEL_AGG0 0
#define SEL_HC   1
#define SEL_T2   2
#define SEL_H2   3
#define SEL_T3   4
#define SEL_OACC 5

template <int SEL>
__device__ __forceinline__ float* pick(float* p) {
    if constexpr (SEL == SEL_AGG0) return g_agg0;
    else if constexpr (SEL == SEL_HC) return g_hc;
    else if constexpr (SEL == SEL_T2) return g_t2;
    else if constexpr (SEL == SEL_H2) return g_h2;
    else if constexpr (SEL == SEL_T3) return g_t3;
    else if constexpr (SEL == SEL_OACC) return g_oacc;
    else return p;
}
template <int SEL>
__device__ __forceinline__ const float* pickc(const float* p) {
    return pick<SEL>(const_cast<float*>(p));
}

static inline int ceil_div_i(long long a, long long b) { return (int)((a + b - 1) / b); }

// ---------------------------------------------------------------------------
// dtype probe: if edge_index is really int32, int64-interpretation of the
// first 64 entries will contain values >= NNODES (hi word = another index).
// ---------------------------------------------------------------------------
__global__ void k_detect(const long long* __restrict__ ei) {
    if (threadIdx.x == 0 && blockIdx.x == 0) {
        int is64 = 1;
        for (int i = 0; i < 64; i++) {
            unsigned long long v = (unsigned long long)ei[i];
            if (v >= (unsigned long long)NNODES) { is64 = 0; break; }
        }
        g_is64 = is64;
    }
}

// ---------------------------------------------------------------------------
// Normalization
// ---------------------------------------------------------------------------
__global__ void k_deg_init() {
    int i = blockIdx.x * blockDim.x + threadIdx.x;
    if (i < NNODES) g_deg[i] = 1.0f;  // self-loop weight
}

__global__ void k_deg_edges(const void* __restrict__ eiv, const float* __restrict__ ew) {
    int e = blockIdx.x * blockDim.x + threadIdx.x;
    if (e < NEDGES) {
        int r, c;
        if (g_is64) {
            const long long* ei = (const long long*)eiv;
            r = (int)ei[e];
            c = (int)ei[NEDGES + e];
        } else {
            const int* ei = (const int*)eiv;
            r = ei[e];
            c = ei[NEDGES + e];
        }
        // Clamp: decode errors become visible wrong answers, never wild writes.
        r = min(max(r, 0), NNODES - 1);
        c = min(max(c, 0), NNODES - 1);
        g_row[e] = r;
        g_col[e] = c;
        atomicAdd(&g_deg[c], ew[e]);   // device-static target
    }
}

__global__ void k_dinv() {
    int i = blockIdx.x * blockDim.x + threadIdx.x;
    if (i < NNODES) g_dinv[i] = rsqrtf(g_deg[i]);  // deg >= 1 always
}

__global__ void k_edge_w(const float* __restrict__ ew) {
    int e = blockIdx.x * blockDim.x + threadIdx.x;
    if (e < NEDGES) g_w[e] = g_dinv[g_row[e]] * ew[e] * g_dinv[g_col[e]];
}

// ---------------------------------------------------------------------------
// Aggregation init: dst[i,f] = (bias ? bias[f] : 0) + dinv[i]^2 * src[i,f]
// ---------------------------------------------------------------------------
template <int F4, bool HAS_BIAS, int SRC, int DST>
__global__ void k_agg_init(const float* src_arg, const float* __restrict__ bias,
                           float* dst_arg) {
    const float4* src = reinterpret_cast<const float4*>(pickc<SRC>(src_arg));
    float4*       dst = reinterpret_cast<float4*>(pick<DST>(dst_arg));
    size_t idx = (size_t)blockIdx.x * blockDim.x + threadIdx.x;
    if (idx >= (size_t)NNODES * F4) return;
    int node = (int)(idx / F4);
    int f4   = (int)(idx % F4);
    float di = g_dinv[node];
    float s  = di * di;
    float4 v = src[idx];
    float4 o;
    if (HAS_BIAS) {
        float4 b = reinterpret_cast<const float4*>(bias)[f4];
        o.x = b.x + s * v.x; o.y = b.y + s * v.y;
        o.z = b.z + s * v.z; o.w = b.w + s * v.w;
    } else {
        o.x = s * v.x; o.y = s * v.y; o.z = s * v.z; o.w = s * v.w;
    }
    dst[idx] = o;
}

// ---------------------------------------------------------------------------
// Edge scatter: dst[col] += w[e] * src[row]   (float4 lanes, TPE = F/4)
// DST is always device-static scratch (never harness memory).
// ---------------------------------------------------------------------------
template <int TPE, int SRC, int DST>
__global__ void k_scatter(const float* src_arg, float* dst_arg) {
    const float* src = pickc<SRC>(src_arg);
    float*       dst = pick<DST>(dst_arg);
    long long tid = (long long)blockIdx.x * blockDim.x + threadIdx.x;
    int e = (int)(tid / TPE);
    if (e >= NEDGES) return;
    int f = (int)(tid % TPE);
    int r = g_row[e];
    int c = g_col[e];
    float w = g_w[e];
    float4 v = reinterpret_cast<const float4*>(src)[(size_t)r * TPE + f];
    float* d = dst + ((size_t)c * TPE + f) * 4;
    atomicAdd(d + 0, w * v.x);
    atomicAdd(d + 1, w * v.y);
    atomicAdd(d + 2, w * v.z);
    atomicAdd(d + 3, w * v.w);
}

// ---------------------------------------------------------------------------
// Tiled fp32 GEMM: C[M,N] = A[M,K] @ B[K,N]
// EPI: 0 = none; 1 = leaky_relu(acc + bias, 0.01)
// RELU_A: relu applied to A elements on load
// ---------------------------------------------------------------------------
template <int BM, int BN, int BK, int TM, int TN, int EPI, bool RELU_A,
          int SELA, int SELC>
__global__ __launch_bounds__((BM / TM) * (BN / TN))
void k_gemm(const float* __restrict__ B, const float* __restrict__ bias,
            long long aOff, long long cOff, int M, int N, int K) {
    const float* A = pickc<SELA>(nullptr) + aOff;
    float*       C = pick<SELC>(nullptr) + cOff;

    constexpr int THREADS = (BM / TM) * (BN / TN);
    __shared__ float As[BK][BM];
    __shared__ float Bs[BK][BN];

    const int tid = threadIdx.x;
    const int bm  = blockIdx.y * BM;
    const int bn  = blockIdx.x * BN;
    const int tx  = tid % (BN / TN);
    const int ty  = tid / (BN / TN);

    float acc[TM][TN];
    #pragma unroll
    for (int i = 0; i < TM; i++)
        #pragma unroll
        for (int j = 0; j < TN; j++) acc[i][j] = 0.0f;

    for (int k0 = 0; k0 < K; k0 += BK) {
        for (int i = tid * 4; i < BM * BK; i += THREADS * 4) {
            int r  = i / BK;
            int cc = i % BK;
            int gr = bm + r;
            float4 v = make_float4(0.f, 0.f, 0.f, 0.f);
            if (gr < M)
                v = *reinterpret_cast<const float4*>(A + (size_t)gr * K + (k0 + cc));
            if (RELU_A) {
                v.x = fmaxf(v.x, 0.f); v.y = fmaxf(v.y, 0.f);
                v.z = fmaxf(v.z, 0.f); v.w = fmaxf(v.w, 0.f);
            }
            As[cc + 0][r] = v.x; As[cc + 1][r] = v.y;
            As[cc + 2][r] = v.z; As[cc + 3][r] = v.w;
        }
        for (int i = tid * 4; i < BK * BN; i += THREADS * 4) {
            int r  = i / BN;
            int cc = i % BN;
            *reinterpret_cast<float4*>(&Bs[r][cc]) =
                *reinterpret_cast<const float4*>(B + (size_t)(k0 + r) * N + bn + cc);
        }
        __syncthreads();

        #pragma unroll
        for (int k = 0; k < BK; k++) {
            float ra[TM], rb[TN];
            #pragma unroll
            for (int i = 0; i < TM; i++) ra[i] = As[k][ty * TM + i];
            #pragma unroll
            for (int j = 0; j < TN; j++) rb[j] = Bs[k][tx * TN + j];
            #pragma unroll
            for (int i = 0; i < TM; i++)
                #pragma unroll
                for (int j = 0; j < TN; j++)
                    acc[i][j] += ra[i] * rb[j];
        }
        __syncthreads();
    }

    #pragma unroll
    for (int i = 0; i < TM; i++) {
        int gm = bm + ty * TM + i;
        if (gm >= M) continue;
        #pragma unroll
        for (int j = 0; j < TN; j++) {
            int gn = bn + tx * TN + j;
            float v = acc[i][j];
            if (EPI == 1) {
                v += bias[gn];
                v = (v > 0.f) ? v : 0.01f * v;
            }
            C[(size_t)gm * N + gn] = v;
        }
    }
}

// ---------------------------------------------------------------------------
// Finalize: out[i] = relu(g_oacc[i]) — plain stores to harness d_out only.
// ---------------------------------------------------------------------------
__global__ void k_finalize(float* __restrict__ out) {
    int i = blockIdx.x * blockDim.x + threadIdx.x;
    const int n4 = NNODES * FF3 / 4;
    if (i < n4) {
        float4 v = reinterpret_cast<const float4*>(g_oacc)[i];
        float4 o;
        o.x = fmaxf(v.x, 0.f); o.y = fmaxf(v.y, 0.f);
        o.z = fmaxf(v.z, 0.f); o.w = fmaxf(v.w, 0.f);
        reinterpret_cast<float4*>(out)[i] = o;
    }
}

// ---------------------------------------------------------------------------
extern "C" void kernel_launch(void* const* d_in, const int* in_sizes, int n_in,
                              void* d_out, int out_size) {
    // Size-keyed input identification (all element counts unique).
    const float* x  = nullptr;
    const void*  ei = nullptr;
    const float* ew = nullptr;
    const float* W1 = nullptr; const float* b1 = nullptr;
    const float* W2 = nullptr; const float* b2 = nullptr;
    const float* W3 = nullptr; const float* b3 = nullptr;
    for (int i = 0; i < n_in; i++) {
        const void* p = d_in[i];
        switch (in_sizes[i]) {
            case NNODES * FF0: x  = (const float*)p; break;   // 25,600,000
            case 2 * NEDGES:   ei = p;               break;   //    400,000
            case NEDGES:       ew = (const float*)p; break;   //    200,000
            case FF0 * FF1:    W1 = (const float*)p; break;   //  1,048,576
            case FF1:          b1 = (const float*)p; break;   //      2,048
            case FF1 * FF2:    W2 = (const float*)p; break;   //    524,288
            case FF2:          b2 = (const float*)p; break;   //        256
            case FF2 * FF3:    W3 = (const float*)p; break;   //     16,384
            case FF3:          b3 = (const float*)p; break;   //         64
            default: break;
        }
    }
    // Positional fallback (should never trigger).
    if (!x)  x  = (const float*)d_in[0];
    if (!ei) ei = d_in[1];
    if (!ew) ew = (const float*)d_in[2];
    if (!W1) W1 = (const float*)d_in[3];
    if (!b1) b1 = (const float*)d_in[4];
    if (!W2) W2 = (const float*)d_in[5];
    if (!b2) b2 = (const float*)d_in[6];
    if (!W3) W3 = (const float*)d_in[7];
    if (!b3) b3 = (const float*)d_in[8];
    float* out = (float*)d_out;

    const int TB = 256;

    // dtype probe + normalization
    k_detect   <<<1, 32>>>((const long long*)ei);
    k_deg_init <<<ceil_div_i(NNODES, TB), TB>>>();
    k_deg_edges<<<ceil_div_i(NEDGES, TB), TB>>>(ei, ew);
    k_dinv     <<<ceil_div_i(NNODES, TB), TB>>>();
    k_edge_w   <<<ceil_div_i(NEDGES, TB), TB>>>(ew);

    // ---- Layer 1 aggregation: agg0 = A_norm @ X (512 feats) ----
    {
        long long tot = (long long)NNODES * (FF0 / 4);
        k_agg_init<FF0 / 4, false, SEL_ARG, SEL_AGG0><<<ceil_div_i(tot, TB), TB>>>(
            x, nullptr, nullptr);
        k_scatter<FF0 / 4, SEL_ARG, SEL_AGG0>
            <<<ceil_div_i((long long)NEDGES * (FF0 / 4), TB), TB>>>(x, nullptr);
    }

    // ---- Chunked GEMM1 -> GEMM2:
    //      hc = leaky_relu(agg0_chunk @ W1 + b1); t2_chunk = hc @ W2 ----
    for (int c = 0; c < NCHUNKS; c++) {
        long long aOff = (long long)c * CHUNK * FF0;
        long long tOff = (long long)c * CHUNK * FF2;
        dim3 g1(FF1 / 128, ceil_div_i(CHUNK, 128));
        k_gemm<128, 128, 16, 8, 8, 1, false, SEL_AGG0, SEL_HC><<<g1, 256>>>(
            W1, b1, aOff, 0, CHUNK, FF1, FF0);
        dim3 g2(FF2 / 128, ceil_div_i(CHUNK, 128));
        k_gemm<128, 128, 16, 8, 8, 0, false, SEL_HC, SEL_T2><<<g2, 256>>>(
            W2, nullptr, 0, tOff, CHUNK, FF2, FF1);
    }

    // ---- Layer 2 aggregation: h2 = b2 + A_norm @ t2 (256 feats) ----
    {
        long long tot = (long long)NNODES * (FF2 / 4);
        k_agg_init<FF2 / 4, true, SEL_T2, SEL_H2><<<ceil_div_i(tot, TB), TB>>>(
            nullptr, b2, nullptr);
        k_scatter<FF2 / 4, SEL_T2, SEL_H2>
            <<<ceil_div_i((long long)NEDGES * (FF2 / 4), TB), TB>>>(nullptr, nullptr);
        // relu(h2) fused into layer-3 GEMM A-load
    }

    // ---- Layer 3: t3 = relu(h2) @ W3 ; oacc = b3 + A_norm @ t3 ; out = relu(oacc)
    {
        dim3 g3(FF3 / 64, ceil_div_i(NNODES, 128));
        k_gemm<128, 64, 16, 8, 4, 0, true, SEL_H2, SEL_T3><<<g3, 256>>>(
            W3, nullptr, 0, 0, NNODES, FF3, FF2);
        long long tot = (long long)NNODES * (FF3 / 4);
        k_agg_init<FF3 / 4, true, SEL_T3, SEL_OACC><<<ceil_div_i(tot, TB), TB>>>(
            nullptr, b3, nullptr);
        k_scatter<FF3 / 4, SEL_T3, SEL_OACC>
            <<<ceil_div_i((long long)NEDGES * (FF3 / 4), TB), TB>>>(nullptr, nullptr);
        k_finalize<<<ceil_div_i(NNODES * FF3 / 4, TB), TB>>>(out);
    }
}

// round 8
// speedup vs baseline: 2.1328x; 2.1328x over previous
#include <cuda_runtime.h>
#include <cuda_bf16.h>
#include <cstddef>
#include <cstdint>

// ---------------------------------------------------------------------------
// pygGCN: 3-layer GCN, N=50000, E=200000, feats 512 -> 2048 -> 256 -> 64
//
//   L1: agg0 = A_norm @ X (512)      ; H1 = leaky_relu(agg0 @ W1 + b1)  [mma.sync]
//   L2: T2   = H1 @ W2 (256)         ; H2 = b2 + A_norm @ T2            [mma.sync]
//   L3: T3   = relu(H2) @ W3 (64)    ; oacc = b3 + A_norm @ T3 ; out = relu(oacc)
//
// GEMM1/2 use warp-level mma.sync bf16 (m16n8k16, sm_80+ PTX -> valid on the
// harness's sm_100 target; tcgen05 is sm_100a-only and NOT available).
// Split-bf16 accuracy: a = a_hi + a_lo; D += Ah*Bh + Ah*Bl + Al*Bh (~2^-16).
// GEMM1 epilogue fuses bias + leaky_relu and writes H1 directly as bf16 hi/lo.
// ---------------------------------------------------------------------------

#define NNODES 50000
#define NEDGES 200000
#define FF0 512
#define FF1 2048
#define FF2 256
#define FF3 64

// ---------------- device scratch (allocation-free) ~750 MB ------------------
__device__ int   g_is64;
__device__ float g_deg [NNODES];
__device__ float g_dinv[NNODES];
__device__ int   g_row [NEDGES];
__device__ int   g_col [NEDGES];
__device__ float g_w   [NEDGES];
__device__ float g_agg0[(size_t)NNODES * FF0];           // 102 MB
__device__ __nv_bfloat16 g_a0h[(size_t)NNODES * FF0];    //  51 MB
__device__ __nv_bfloat16 g_a0l[(size_t)NNODES * FF0];    //  51 MB
__device__ __nv_bfloat16 g_w1h[(size_t)FF0 * FF1];       //   2 MB  [K][N] native
__device__ __nv_bfloat16 g_w1l[(size_t)FF0 * FF1];
__device__ __nv_bfloat16 g_w2h[(size_t)FF1 * FF2];       //   1 MB  [K][N] native
__device__ __nv_bfloat16 g_w2l[(size_t)FF1 * FF2];
__device__ __nv_bfloat16 g_h1h[(size_t)NNODES * FF1];    // 205 MB
__device__ __nv_bfloat16 g_h1l[(size_t)NNODES * FF1];    // 205 MB
__device__ float g_t2  [(size_t)NNODES * FF2];           //  51 MB
__device__ float g_h2  [(size_t)NNODES * FF2];           //  51 MB
__device__ float g_t3  [(size_t)NNODES * FF3];           //  13 MB
__device__ float g_oacc[(size_t)NNODES * FF3];           //  13 MB

// selectors for SIMT kernels
#define SEL_ARG  (-1)
#define SEL_AGG0 0
#define SEL_T2   2
#define SEL_H2   3
#define SEL_T3   4
#define SEL_OACC 5

template <int SEL>
__device__ __forceinline__ float* pick(float* p) {
    if constexpr (SEL == SEL_AGG0) return g_agg0;
    else if constexpr (SEL == SEL_T2) return g_t2;
    else if constexpr (SEL == SEL_H2) return g_h2;
    else if constexpr (SEL == SEL_T3) return g_t3;
    else if constexpr (SEL == SEL_OACC) return g_oacc;
    else return p;
}
template <int SEL>
__device__ __forceinline__ const float* pickc(const float* p) {
    return pick<SEL>(const_cast<float*>(p));
}

static inline int ceil_div_i(long long a, long long b) { return (int)((a + b - 1) / b); }

// ---------------------------- mma helpers ----------------------------------
__device__ __forceinline__ uint32_t smem_u32(const void* p) {
    uint32_t a;
    asm("{ .reg .u64 t; cvta.to.shared.u64 t, %1; cvt.u32.u64 %0, t; }" : "=r"(a) : "l"(p));
    return a;
}
__device__ __forceinline__ void ldsm_x4(uint32_t* r, uint32_t addr) {
    asm volatile("ldmatrix.sync.aligned.m8n8.x4.shared.b16 {%0,%1,%2,%3}, [%4];"
        : "=r"(r[0]), "=r"(r[1]), "=r"(r[2]), "=r"(r[3]) : "r"(addr));
}
__device__ __forceinline__ void ldsm_x4_t(uint32_t* r, uint32_t addr) {
    asm volatile("ldmatrix.sync.aligned.m8n8.x4.trans.shared.b16 {%0,%1,%2,%3}, [%4];"
        : "=r"(r[0]), "=r"(r[1]), "=r"(r[2]), "=r"(r[3]) : "r"(addr));
}
__device__ __forceinline__ void mma16816(float* c, const uint32_t* a, const uint32_t* b) {
    asm volatile("mma.sync.aligned.m16n8k16.row.col.f32.bf16.bf16.f32 "
        "{%0,%1,%2,%3}, {%4,%5,%6,%7}, {%8,%9}, {%0,%1,%2,%3};"
        : "+f"(c[0]), "+f"(c[1]), "+f"(c[2]), "+f"(c[3])
        : "r"(a[0]), "r"(a[1]), "r"(a[2]), "r"(a[3]), "r"(b[0]), "r"(b[1]));
}
__device__ __forceinline__ void split_bf16(float v, __nv_bfloat16& h, __nv_bfloat16& l) {
    h = __float2bfloat16(v);
    l = __float2bfloat16(v - __bfloat162float(h));
}

// ---------------------------------------------------------------------------
// Split-bf16 tensor GEMM: C[M,N] = A[M,K] @ B[K,N] via 3 bf16 products.
// Tile 128x128x32, 256 threads, 8 warps (4 m x 2 n), warp tile 32x64.
// MODE 1: A = a0h/a0l (K=512),  B = W1 (N=2048); epi: bias+leaky -> h1h/h1l
// MODE 2: A = h1h/h1l (K=2048), B = W2 (N=256);  epi: plain fp32 -> t2
// ---------------------------------------------------------------------------
#define ASTR 40    // A smem row stride (bf16) — conflict-free ldmatrix
#define BSTR 136   // B smem row stride (bf16)

template <int MODE>
__global__ __launch_bounds__(256)
void mma_gemm(const float* __restrict__ bias) {
    constexpr int KTOT = (MODE == 1) ? FF0 : FF1;
    constexpr int NTOT = (MODE == 1) ? FF1 : FF2;
    const __nv_bfloat16* Ah = (MODE == 1) ? g_a0h : g_h1h;
    const __nv_bfloat16* Al = (MODE == 1) ? g_a0l : g_h1l;
    const __nv_bfloat16* Bh = (MODE == 1) ? g_w1h : g_w2h;
    const __nv_bfloat16* Bl = (MODE == 1) ? g_w1l : g_w2l;

    __shared__ __nv_bfloat16 sAh[128][ASTR];
    __shared__ __nv_bfloat16 sAl[128][ASTR];
    __shared__ __nv_bfloat16 sBh[32][BSTR];
    __shared__ __nv_bfloat16 sBl[32][BSTR];

    const int tid = threadIdx.x;
    const int wid = tid >> 5, lane = tid & 31;
    const int warp_m = wid & 3, warp_n = wid >> 2;
    const int bm = blockIdx.y * 128, bn = blockIdx.x * 128;
    const int g = lane >> 2, t4 = lane & 3;

    float acc[2][8][4];
    #pragma unroll
    for (int i = 0; i < 2; i++)
        #pragma unroll
        for (int j = 0; j < 8; j++)
            #pragma unroll
            for (int v = 0; v < 4; v++) acc[i][j][v] = 0.f;

    for (int k0 = 0; k0 < KTOT; k0 += 32) {
        // A tile: 128 rows x 32 cols (4 x uint4/row), hi+lo
        #pragma unroll
        for (int j = 0; j < 2; j++) {
            int t = tid + j * 256;           // 0..511
            int r = t >> 2, c = (t & 3) * 8;
            uint4 vh = make_uint4(0, 0, 0, 0), vl = vh;
            if (bm + r < NNODES) {
                size_t idx = (size_t)(bm + r) * KTOT + k0 + c;
                vh = *reinterpret_cast<const uint4*>(Ah + idx);
                vl = *reinterpret_cast<const uint4*>(Al + idx);
            }
            *reinterpret_cast<uint4*>(&sAh[r][c]) = vh;
            *reinterpret_cast<uint4*>(&sAl[r][c]) = vl;
        }
        // B tile: 32 rows x 128 cols (16 x uint4/row), hi+lo
        #pragma unroll
        for (int j = 0; j < 2; j++) {
            int t = tid + j * 256;
            int r = t >> 4, c = (t & 15) * 8;
            size_t idx = (size_t)(k0 + r) * NTOT + bn + c;
            *reinterpret_cast<uint4*>(&sBh[r][c]) =
                *reinterpret_cast<const uint4*>(Bh + idx);
            *reinterpret_cast<uint4*>(&sBl[r][c]) =
                *reinterpret_cast<const uint4*>(Bl + idx);
        }
        __syncthreads();

        #pragma unroll
        for (int kk = 0; kk < 2; kk++) {
            const int k16 = kk * 16;
            uint32_t ah[2][4], al[2][4], bh[4][4], bl[4][4];
            #pragma unroll
            for (int mt = 0; mt < 2; mt++) {
                int rr = warp_m * 32 + mt * 16 + (lane & 15);
                int cc = k16 + (lane >> 4) * 8;
                ldsm_x4(ah[mt], smem_u32(&sAh[rr][cc]));
                ldsm_x4(al[mt], smem_u32(&sAl[rr][cc]));
            }
            #pragma unroll
            for (int np = 0; np < 4; np++) {
                int rr = k16 + (lane & 15);
                int cc = warp_n * 64 + np * 16 + (lane >> 4) * 8;
                ldsm_x4_t(bh[np], smem_u32(&sBh[rr][cc]));
                ldsm_x4_t(bl[np], smem_u32(&sBl[rr][cc]));
            }
            #pragma unroll
            for (int mt = 0; mt < 2; mt++)
                #pragma unroll
                for (int nt = 0; nt < 8; nt++) {
                    const uint32_t* bhp = bh[nt >> 1] + (nt & 1) * 2;
                    const uint32_t* blp = bl[nt >> 1] + (nt & 1) * 2;
                    mma16816(acc[mt][nt], ah[mt], bhp);
                    mma16816(acc[mt][nt], ah[mt], blp);
                    mma16816(acc[mt][nt], al[mt], bhp);
                }
        }
        __syncthreads();
    }

    // ---- epilogue ----
    #pragma unroll
    for (int mt = 0; mt < 2; mt++)
        #pragma unroll
        for (int nt = 0; nt < 8; nt++) {
            int col  = bn + warp_n * 64 + nt * 8 + t4 * 2;
            int row0 = bm + warp_m * 32 + mt * 16 + g;
            #pragma unroll
            for (int h = 0; h < 2; h++) {
                int row = row0 + h * 8;
                if (row >= NNODES) continue;
                float v0 = acc[mt][nt][h * 2 + 0];
                float v1 = acc[mt][nt][h * 2 + 1];
                if constexpr (MODE == 1) {
                    v0 += bias[col];     v1 += bias[col + 1];
                    v0 = (v0 > 0.f) ? v0 : 0.01f * v0;
                    v1 = (v1 > 0.f) ? v1 : 0.01f * v1;
                    __nv_bfloat162 hb, lb;
                    split_bf16(v0, hb.x, lb.x);
                    split_bf16(v1, hb.y, lb.y);
                    size_t o = (size_t)row * NTOT + col;
                    *reinterpret_cast<__nv_bfloat162*>(g_h1h + o) = hb;
                    *reinterpret_cast<__nv_bfloat162*>(g_h1l + o) = lb;
                } else {
                    float2 f = make_float2(v0, v1);
                    *reinterpret_cast<float2*>(g_t2 + (size_t)row * NTOT + col) = f;
                }
            }
        }
}

// ---------------------------------------------------------------------------
// Conversion kernels (hi/lo splits; W kept in native [K][N] layout)
// ---------------------------------------------------------------------------
__global__ void k_conv_a() {
    size_t i8 = ((size_t)blockIdx.x * blockDim.x + threadIdx.x) * 8;
    if (i8 >= (size_t)NNODES * FF0) return;
    float4 v0 = *reinterpret_cast<const float4*>(g_agg0 + i8);
    float4 v1 = *reinterpret_cast<const float4*>(g_agg0 + i8 + 4);
    union { __nv_bfloat16 b[8]; uint4 u; } hb, lb;
    float vs[8] = {v0.x, v0.y, v0.z, v0.w, v1.x, v1.y, v1.z, v1.w};
    #pragma unroll
    for (int t = 0; t < 8; t++) split_bf16(vs[t], hb.b[t], lb.b[t]);
    *reinterpret_cast<uint4*>(g_a0h + i8) = hb.u;
    *reinterpret_cast<uint4*>(g_a0l + i8) = lb.u;
}
__global__ void k_conv_w1(const float* __restrict__ W1) {
    int i = blockIdx.x * blockDim.x + threadIdx.x;
    if (i < FF0 * FF1) split_bf16(W1[i], g_w1h[i], g_w1l[i]);
}
__global__ void k_conv_w2(const float* __restrict__ W2) {
    int i = blockIdx.x * blockDim.x + threadIdx.x;
    if (i < FF1 * FF2) split_bf16(W2[i], g_w2h[i], g_w2l[i]);
}

// ---------------------------------------------------------------------------
// Normalization / graph kernels (unchanged from passing R6)
// ---------------------------------------------------------------------------
__global__ void k_detect(const long long* __restrict__ ei) {
    if (threadIdx.x == 0 && blockIdx.x == 0) {
        int is64 = 1;
        for (int i = 0; i < 64; i++) {
            unsigned long long v = (unsigned long long)ei[i];
            if (v >= (unsigned long long)NNODES) { is64 = 0; break; }
        }
        g_is64 = is64;
    }
}
__global__ void k_deg_init() {
    int i = blockIdx.x * blockDim.x + threadIdx.x;
    if (i < NNODES) g_deg[i] = 1.0f;
}
__global__ void k_deg_edges(const void* __restrict__ eiv, const float* __restrict__ ew) {
    int e = blockIdx.x * blockDim.x + threadIdx.x;
    if (e < NEDGES) {
        int r, c;
        if (g_is64) {
            const long long* ei = (const long long*)eiv;
            r = (int)ei[e]; c = (int)ei[NEDGES + e];
        } else {
            const int* ei = (const int*)eiv;
            r = ei[e]; c = ei[NEDGES + e];
        }
        r = min(max(r, 0), NNODES - 1);
        c = min(max(c, 0), NNODES - 1);
        g_row[e] = r; g_col[e] = c;
        atomicAdd(&g_deg[c], ew[e]);
    }
}
__global__ void k_dinv() {
    int i = blockIdx.x * blockDim.x + threadIdx.x;
    if (i < NNODES) g_dinv[i] = rsqrtf(g_deg[i]);
}
__global__ void k_edge_w(const float* __restrict__ ew) {
    int e = blockIdx.x * blockDim.x + threadIdx.x;
    if (e < NEDGES) g_w[e] = g_dinv[g_row[e]] * ew[e] * g_dinv[g_col[e]];
}

template <int F4, bool HAS_BIAS, int SRC, int DST>
__global__ void k_agg_init(const float* src_arg, const float* __restrict__ bias,
                           float* dst_arg) {
    const float4* src = reinterpret_cast<const float4*>(pickc<SRC>(src_arg));
    float4*       dst = reinterpret_cast<float4*>(pick<DST>(dst_arg));
    size_t idx = (size_t)blockIdx.x * blockDim.x + threadIdx.x;
    if (idx >= (size_t)NNODES * F4) return;
    int node = (int)(idx / F4);
    int f4   = (int)(idx % F4);
    float di = g_dinv[node];
    float s  = di * di;
    float4 v = src[idx];
    float4 o;
    if (HAS_BIAS) {
        float4 b = reinterpret_cast<const float4*>(bias)[f4];
        o.x = b.x + s * v.x; o.y = b.y + s * v.y;
        o.z = b.z + s * v.z; o.w = b.w + s * v.w;
    } else {
        o.x = s * v.x; o.y = s * v.y; o.z = s * v.z; o.w = s * v.w;
    }
    dst[idx] = o;
}

template <int TPE, int SRC, int DST>
__global__ void k_scatter(const float* src_arg, float* dst_arg) {
    const float* src = pickc<SRC>(src_arg);
    float*       dst = pick<DST>(dst_arg);
    long long tid = (long long)blockIdx.x * blockDim.x + threadIdx.x;
    int e = (int)(tid / TPE);
    if (e >= NEDGES) return;
    int f = (int)(tid % TPE);
    int r = g_row[e];
    int c = g_col[e];
    float w = g_w[e];
    float4 v = reinterpret_cast<const float4*>(src)[(size_t)r * TPE + f];
    float* d = dst + ((size_t)c * TPE + f) * 4;
    atomicAdd(d + 0, w * v.x);
    atomicAdd(d + 1, w * v.y);
    atomicAdd(d + 2, w * v.z);
    atomicAdd(d + 3, w * v.w);
}

// SIMT GEMM (layer 3 only: 50000x64x256 with relu'd A)
template <int BM, int BN, int BK, int TM, int TN, int EPI, bool RELU_A,
          int SELA, int SELC>
__global__ __launch_bounds__((BM / TM) * (BN / TN))
void k_gemm(const float* __restrict__ B, const float* __restrict__ bias,
            long long aOff, long long cOff, int M, int N, int K) {
    const float* A = pickc<SELA>(nullptr) + aOff;
    float*       C = pick<SELC>(nullptr) + cOff;
    constexpr int THREADS = (BM / TM) * (BN / TN);
    __shared__ float As[BK][BM];
    __shared__ float Bs[BK][BN];
    const int tid = threadIdx.x;
    const int bm  = blockIdx.y * BM;
    const int bn  = blockIdx.x * BN;
    const int tx  = tid % (BN / TN);
    const int ty  = tid / (BN / TN);
    float acc[TM][TN];
    #pragma unroll
    for (int i = 0; i < TM; i++)
        #pragma unroll
        for (int j = 0; j < TN; j++) acc[i][j] = 0.0f;
    for (int k0 = 0; k0 < K; k0 += BK) {
        for (int i = tid * 4; i < BM * BK; i += THREADS * 4) {
            int r = i / BK, cc = i % BK, gr = bm + r;
            float4 v = make_float4(0.f, 0.f, 0.f, 0.f);
            if (gr < M)
                v = *reinterpret_cast<const float4*>(A + (size_t)gr * K + (k0 + cc));
            if (RELU_A) {
                v.x = fmaxf(v.x, 0.f); v.y = fmaxf(v.y, 0.f);
                v.z = fmaxf(v.z, 0.f); v.w = fmaxf(v.w, 0.f);
            }
            As[cc + 0][r] = v.x; As[cc + 1][r] = v.y;
            As[cc + 2][r] = v.z; As[cc + 3][r] = v.w;
        }
        for (int i = tid * 4; i < BK * BN; i += THREADS * 4) {
            int r = i / BN, cc = i % BN;
            *reinterpret_cast<float4*>(&Bs[r][cc]) =
                *reinterpret_cast<const float4*>(B + (size_t)(k0 + r) * N + bn + cc);
        }
        __syncthreads();
        #pragma unroll
        for (int k = 0; k < BK; k++) {
            float ra[TM], rb[TN];
            #pragma unroll
            for (int i = 0; i < TM; i++) ra[i] = As[k][ty * TM + i];
            #pragma unroll
            for (int j = 0; j < TN; j++) rb[j] = Bs[k][tx * TN + j];
            #pragma unroll
            for (int i = 0; i < TM; i++)
                #pragma unroll
                for (int j = 0; j < TN; j++)
                    acc[i][j] += ra[i] * rb[j];
        }
        __syncthreads();
    }
    #pragma unroll
    for (int i = 0; i < TM; i++) {
        int gm = bm + ty * TM + i;
        if (gm >= M) continue;
        #pragma unroll
        for (int j = 0; j < TN; j++) {
            int gn = bn + tx * TN + j;
            float v = acc[i][j];
            if (EPI == 1) {
                v += bias[gn];
                v = (v > 0.f) ? v : 0.01f * v;
            }
            C[(size_t)gm * N + gn] = v;
        }
    }
}

__global__ void k_finalize(float* __restrict__ out) {
    int i = blockIdx.x * blockDim.x + threadIdx.x;
    const int n4 = NNODES * FF3 / 4;
    if (i < n4) {
        float4 v = reinterpret_cast<const float4*>(g_oacc)[i];
        float4 o;
        o.x = fmaxf(v.x, 0.f); o.y = fmaxf(v.y, 0.f);
        o.z = fmaxf(v.z, 0.f); o.w = fmaxf(v.w, 0.f);
        reinterpret_cast<float4*>(out)[i] = o;
    }
}

// ---------------------------------------------------------------------------
extern "C" void kernel_launch(void* const* d_in, const int* in_sizes, int n_in,
                              void* d_out, int out_size) {
    const float* x  = nullptr;
    const void*  ei = nullptr;
    const float* ew = nullptr;
    const float* W1 = nullptr; const float* b1 = nullptr;
    const float* W2 = nullptr; const float* b2 = nullptr;
    const float* W3 = nullptr; const float* b3 = nullptr;
    for (int i = 0; i < n_in; i++) {
        const void* p = d_in[i];
        switch (in_sizes[i]) {
            case NNODES * FF0: x  = (const float*)p; break;
            case 2 * NEDGES:   ei = p;               break;
            case NEDGES:       ew = (const float*)p; break;
            case FF0 * FF1:    W1 = (const float*)p; break;
            case FF1:          b1 = (const float*)p; break;
            case FF1 * FF2:    W2 = (const float*)p; break;
            case FF2:          b2 = (const float*)p; break;
            case FF2 * FF3:    W3 = (const float*)p; break;
            case FF3:          b3 = (const float*)p; break;
            default: break;
        }
    }
    if (!x)  x  = (const float*)d_in[0];
    if (!ei) ei = d_in[1];
    if (!ew) ew = (const float*)d_in[2];
    if (!W1) W1 = (const float*)d_in[3];
    if (!b1) b1 = (const float*)d_in[4];
    if (!W2) W2 = (const float*)d_in[5];
    if (!b2) b2 = (const float*)d_in[6];
    if (!W3) W3 = (const float*)d_in[7];
    if (!b3) b3 = (const float*)d_in[8];
    float* out = (float*)d_out;

    const int TB = 256;

    k_detect   <<<1, 32>>>((const long long*)ei);
    k_deg_init <<<ceil_div_i(NNODES, TB), TB>>>();
    k_deg_edges<<<ceil_div_i(NEDGES, TB), TB>>>(ei, ew);
    k_dinv     <<<ceil_div_i(NNODES, TB), TB>>>();
    k_edge_w   <<<ceil_div_i(NEDGES, TB), TB>>>(ew);

    // weight splits (native layout)
    k_conv_w1<<<ceil_div_i(FF0 * FF1, TB), TB>>>(W1);
    k_conv_w2<<<ceil_div_i(FF1 * FF2, TB), TB>>>(W2);

    // ---- L1 aggregation: agg0 = A_norm @ X, then split to bf16 hi/lo ----
    {
        long long tot = (long long)NNODES * (FF0 / 4);
        k_agg_init<FF0 / 4, false, SEL_ARG, SEL_AGG0><<<ceil_div_i(tot, TB), TB>>>(
            x, nullptr, nullptr);
        k_scatter<FF0 / 4, SEL_ARG, SEL_AGG0>
            <<<ceil_div_i((long long)NEDGES * (FF0 / 4), TB), TB>>>(x, nullptr);
        k_conv_a<<<ceil_div_i((long long)NNODES * FF0 / 8, TB), TB>>>();
    }

    // ---- tensor GEMM1: H1 = leaky_relu(agg0 @ W1 + b1)  [bf16 hi/lo out] ----
    {
        dim3 g(FF1 / 128, ceil_div_i(NNODES, 128));   // (16, 391)
        mma_gemm<1><<<g, 256>>>(b1);
    }
    // ---- tensor GEMM2: t2 = H1 @ W2 ----
    {
        dim3 g(FF2 / 128, ceil_div_i(NNODES, 128));   // (2, 391)
        mma_gemm<2><<<g, 256>>>(nullptr);
    }

    // ---- L2 aggregation: h2 = b2 + A_norm @ t2 ----
    {
        long long tot = (long long)NNODES * (FF2 / 4);
        k_agg_init<FF2 / 4, true, SEL_T2, SEL_H2><<<ceil_div_i(tot, TB), TB>>>(
            nullptr, b2, nullptr);
        k_scatter<FF2 / 4, SEL_T2, SEL_H2>
            <<<ceil_div_i((long long)NEDGES * (FF2 / 4), TB), TB>>>(nullptr, nullptr);
    }

    // ---- L3: t3 = relu(h2) @ W3 ; oacc = b3 + A_norm @ t3 ; out = relu(oacc)
    {
        dim3 g3(FF3 / 64, ceil_div_i(NNODES, 128));
        k_gemm<128, 64, 16, 8, 4, 0, true, SEL_H2, SEL_T3><<<g3, 256>>>(
            W3, nullptr, 0, 0, NNODES, FF3, FF2);
        long long tot = (long long)NNODES * (FF3 / 4);
        k_agg_init<FF3 / 4, true, SEL_T3, SEL_OACC><<<ceil_div_i(tot, TB), TB>>>(
            nullptr, b3, nullptr);
        k_scatter<FF3 / 4, SEL_T3, SEL_OACC>
            <<<ceil_div_i((long long)NEDGES * (FF3 / 4), TB), TB>>>(nullptr, nullptr);
        k_finalize<<<ceil_div_i(NNODES * FF3 / 4, TB), TB>>>(out);
    }
}

// round 16
// speedup vs baseline: 2.1414x; 1.0040x over previous
#include <cuda_runtime.h>
#include <cuda_bf16.h>
#include <cstddef>
#include <cstdint>

// ---------------------------------------------------------------------------
// pygGCN: 3-layer GCN, N=50000, E=200000, feats 512 -> 2048 -> 256 -> 64
//
// BISECTION ROUND: this is the exact R8 source (measured 2703 us, rel_err
// 9.6e-6) resubmitted unchanged to distinguish "CSR-gather additions contain
// an unfound wild write" from "broker/fleet failure streak". R14/R15 (R8 +
// CSR gather) died at container level twice each despite clean audits.
//
//   L1: agg0 = A_norm @ X (512)      ; H1 = leaky_relu(agg0 @ W1 + b1)  [mma.sync]
//   L2: T2   = H1 @ W2 (256)         ; H2 = b2 + A_norm @ T2            [mma.sync]
//   L3: T3   = relu(H2) @ W3 (64)    ; oacc = b3 + A_norm @ T3 ; out = relu(oacc)
//
// GEMM1/2 use warp-level mma.sync bf16 (m16n8k16). Split-bf16 accuracy:
// a = a_hi + a_lo; D += Ah*Bh + Ah*Bl + Al*Bh (~2^-16).
// ---------------------------------------------------------------------------

#define NNODES 50000
#define NEDGES 200000
#define FF0 512
#define FF1 2048
#define FF2 256
#define FF3 64

// ---------------- device scratch (allocation-free) ~750 MB ------------------
__device__ int   g_is64;
__device__ float g_deg [NNODES];
__device__ float g_dinv[NNODES];
__device__ int   g_row [NEDGES];
__device__ int   g_col [NEDGES];
__device__ float g_w   [NEDGES];
__device__ float g_agg0[(size_t)NNODES * FF0];           // 102 MB
__device__ __nv_bfloat16 g_a0h[(size_t)NNODES * FF0];    //  51 MB
__device__ __nv_bfloat16 g_a0l[(size_t)NNODES * FF0];    //  51 MB
__device__ __nv_bfloat16 g_w1h[(size_t)FF0 * FF1];       //   2 MB  [K][N] native
__device__ __nv_bfloat16 g_w1l[(size_t)FF0 * FF1];
__device__ __nv_bfloat16 g_w2h[(size_t)FF1 * FF2];       //   1 MB  [K][N] native
__device__ __nv_bfloat16 g_w2l[(size_t)FF1 * FF2];
__device__ __nv_bfloat16 g_h1h[(size_t)NNODES * FF1];    // 205 MB
__device__ __nv_bfloat16 g_h1l[(size_t)NNODES * FF1];    // 205 MB
__device__ float g_t2  [(size_t)NNODES * FF2];           //  51 MB
__device__ float g_h2  [(size_t)NNODES * FF2];           //  51 MB
__device__ float g_t3  [(size_t)NNODES * FF3];           //  13 MB
__device__ float g_oacc[(size_t)NNODES * FF3];           //  13 MB

// selectors for SIMT kernels
#define SEL_ARG  (-1)
#define SEL_AGG0 0
#define SEL_T2   2
#define SEL_H2   3
#define SEL_T3   4
#define SEL_OACC 5

template <int SEL>
__device__ __forceinline__ float* pick(float* p) {
    if constexpr (SEL == SEL_AGG0) return g_agg0;
    else if constexpr (SEL == SEL_T2) return g_t2;
    else if constexpr (SEL == SEL_H2) return g_h2;
    else if constexpr (SEL == SEL_T3) return g_t3;
    else if constexpr (SEL == SEL_OACC) return g_oacc;
    else return p;
}
template <int SEL>
__device__ __forceinline__ const float* pickc(const float* p) {
    return pick<SEL>(const_cast<float*>(p));
}

static inline int ceil_div_i(long long a, long long b) { return (int)((a + b - 1) / b); }

// ---------------------------- mma helpers ----------------------------------
__device__ __forceinline__ uint32_t smem_u32(const void* p) {
    uint32_t a;
    asm("{ .reg .u64 t; cvta.to.shared.u64 t, %1; cvt.u32.u64 %0, t; }" : "=r"(a) : "l"(p));
    return a;
}
__device__ __forceinline__ void ldsm_x4(uint32_t* r, uint32_t addr) {
    asm volatile("ldmatrix.sync.aligned.m8n8.x4.shared.b16 {%0,%1,%2,%3}, [%4];"
        : "=r"(r[0]), "=r"(r[1]), "=r"(r[2]), "=r"(r[3]) : "r"(addr));
}
__device__ __forceinline__ void ldsm_x4_t(uint32_t* r, uint32_t addr) {
    asm volatile("ldmatrix.sync.aligned.m8n8.x4.trans.shared.b16 {%0,%1,%2,%3}, [%4];"
        : "=r"(r[0]), "=r"(r[1]), "=r"(r[2]), "=r"(r[3]) : "r"(addr));
}
__device__ __forceinline__ void mma16816(float* c, const uint32_t* a, const uint32_t* b) {
    asm volatile("mma.sync.aligned.m16n8k16.row.col.f32.bf16.bf16.f32 "
        "{%0,%1,%2,%3}, {%4,%5,%6,%7}, {%8,%9}, {%0,%1,%2,%3};"
        : "+f"(c[0]), "+f"(c[1]), "+f"(c[2]), "+f"(c[3])
        : "r"(a[0]), "r"(a[1]), "r"(a[2]), "r"(a[3]), "r"(b[0]), "r"(b[1]));
}
__device__ __forceinline__ void split_bf16(float v, __nv_bfloat16& h, __nv_bfloat16& l) {
    h = __float2bfloat16(v);
    l = __float2bfloat16(v - __bfloat162float(h));
}

// ---------------------------------------------------------------------------
// Split-bf16 tensor GEMM: C[M,N] = A[M,K] @ B[K,N] via 3 bf16 products.
// Tile 128x128x32, 256 threads, 8 warps (4 m x 2 n), warp tile 32x64.
// MODE 1: A = a0h/a0l (K=512),  B = W1 (N=2048); epi: bias+leaky -> h1h/h1l
// MODE 2: A = h1h/h1l (K=2048), B = W2 (N=256);  epi: plain fp32 -> t2
// ---------------------------------------------------------------------------
#define ASTR 40    // A smem row stride (bf16) — conflict-free ldmatrix
#define BSTR 136   // B smem row stride (bf16)

template <int MODE>
__global__ __launch_bounds__(256)
void mma_gemm(const float* __restrict__ bias) {
    constexpr int KTOT = (MODE == 1) ? FF0 : FF1;
    constexpr int NTOT = (MODE == 1) ? FF1 : FF2;
    const __nv_bfloat16* Ah = (MODE == 1) ? g_a0h : g_h1h;
    const __nv_bfloat16* Al = (MODE == 1) ? g_a0l : g_h1l;
    const __nv_bfloat16* Bh = (MODE == 1) ? g_w1h : g_w2h;
    const __nv_bfloat16* Bl = (MODE == 1) ? g_w1l : g_w2l;

    __shared__ __nv_bfloat16 sAh[128][ASTR];
    __shared__ __nv_bfloat16 sAl[128][ASTR];
    __shared__ __nv_bfloat16 sBh[32][BSTR];
    __shared__ __nv_bfloat16 sBl[32][BSTR];

    const int tid = threadIdx.x;
    const int wid = tid >> 5, lane = tid & 31;
    const int warp_m = wid & 3, warp_n = wid >> 2;
    const int bm = blockIdx.y * 128, bn = blockIdx.x * 128;
    const int g = lane >> 2, t4 = lane & 3;

    float acc[2][8][4];
    #pragma unroll
    for (int i = 0; i < 2; i++)
        #pragma unroll
        for (int j = 0; j < 8; j++)
            #pragma unroll
            for (int v = 0; v < 4; v++) acc[i][j][v] = 0.f;

    for (int k0 = 0; k0 < KTOT; k0 += 32) {
        // A tile: 128 rows x 32 cols (4 x uint4/row), hi+lo
        #pragma unroll
        for (int j = 0; j < 2; j++) {
            int t = tid + j * 256;           // 0..511
            int r = t >> 2, c = (t & 3) * 8;
            uint4 vh = make_uint4(0, 0, 0, 0), vl = vh;
            if (bm + r < NNODES) {
                size_t idx = (size_t)(bm + r) * KTOT + k0 + c;
                vh = *reinterpret_cast<const uint4*>(Ah + idx);
                vl = *reinterpret_cast<const uint4*>(Al + idx);
            }
            *reinterpret_cast<uint4*>(&sAh[r][c]) = vh;
            *reinterpret_cast<uint4*>(&sAl[r][c]) = vl;
        }
        // B tile: 32 rows x 128 cols (16 x uint4/row), hi+lo
        #pragma unroll
        for (int j = 0; j < 2; j++) {
            int t = tid + j * 256;
            int r = t >> 4, c = (t & 15) * 8;
            size_t idx = (size_t)(k0 + r) * NTOT + bn + c;
            *reinterpret_cast<uint4*>(&sBh[r][c]) =
                *reinterpret_cast<const uint4*>(Bh + idx);
            *reinterpret_cast<uint4*>(&sBl[r][c]) =
                *reinterpret_cast<const uint4*>(Bl + idx);
        }
        __syncthreads();

        #pragma unroll
        for (int kk = 0; kk < 2; kk++) {
            const int k16 = kk * 16;
            uint32_t ah[2][4], al[2][4], bh[4][4], bl[4][4];
            #pragma unroll
            for (int mt = 0; mt < 2; mt++) {
                int rr = warp_m * 32 + mt * 16 + (lane & 15);
                int cc = k16 + (lane >> 4) * 8;
                ldsm_x4(ah[mt], smem_u32(&sAh[rr][cc]));
                ldsm_x4(al[mt], smem_u32(&sAl[rr][cc]));
            }
            #pragma unroll
            for (int np = 0; np < 4; np++) {
                int rr = k16 + (lane & 15);
                int cc = warp_n * 64 + np * 16 + (lane >> 4) * 8;
                ldsm_x4_t(bh[np], smem_u32(&sBh[rr][cc]));
                ldsm_x4_t(bl[np], smem_u32(&sBl[rr][cc]));
            }
            #pragma unroll
            for (int mt = 0; mt < 2; mt++)
                #pragma unroll
                for (int nt = 0; nt < 8; nt++) {
                    const uint32_t* bhp = bh[nt >> 1] + (nt & 1) * 2;
                    const uint32_t* blp = bl[nt >> 1] + (nt & 1) * 2;
                    mma16816(acc[mt][nt], ah[mt], bhp);
                    mma16816(acc[mt][nt], ah[mt], blp);
                    mma16816(acc[mt][nt], al[mt], bhp);
                }
        }
        __syncthreads();
    }

    // ---- epilogue ----
    #pragma unroll
    for (int mt = 0; mt < 2; mt++)
        #pragma unroll
        for (int nt = 0; nt < 8; nt++) {
            int col  = bn + warp_n * 64 + nt * 8 + t4 * 2;
            int row0 = bm + warp_m * 32 + mt * 16 + g;
            #pragma unroll
            for (int h = 0; h < 2; h++) {
                int row = row0 + h * 8;
                if (row >= NNODES) continue;
                float v0 = acc[mt][nt][h * 2 + 0];
                float v1 = acc[mt][nt][h * 2 + 1];
                if constexpr (MODE == 1) {
                    v0 += bias[col];     v1 += bias[col + 1];
                    v0 = (v0 > 0.f) ? v0 : 0.01f * v0;
                    v1 = (v1 > 0.f) ? v1 : 0.01f * v1;
                    __nv_bfloat162 hb, lb;
                    split_bf16(v0, hb.x, lb.x);
                    split_bf16(v1, hb.y, lb.y);
                    size_t o = (size_t)row * NTOT + col;
                    *reinterpret_cast<__nv_bfloat162*>(g_h1h + o) = hb;
                    *reinterpret_cast<__nv_bfloat162*>(g_h1l + o) = lb;
                } else {
                    float2 f = make_float2(v0, v1);
                    *reinterpret_cast<float2*>(g_t2 + (size_t)row * NTOT + col) = f;
                }
            }
        }
}

// ---------------------------------------------------------------------------
// Conversion kernels (hi/lo splits; W kept in native [K][N] layout)
// ---------------------------------------------------------------------------
__global__ void k_conv_a() {
    size_t i8 = ((size_t)blockIdx.x * blockDim.x + threadIdx.x) * 8;
    if (i8 >= (size_t)NNODES * FF0) return;
    float4 v0 = *reinterpret_cast<const float4*>(g_agg0 + i8);
    float4 v1 = *reinterpret_cast<const float4*>(g_agg0 + i8 + 4);
    union { __nv_bfloat16 b[8]; uint4 u; } hb, lb;
    float vs[8] = {v0.x, v0.y, v0.z, v0.w, v1.x, v1.y, v1.z, v1.w};
    #pragma unroll
    for (int t = 0; t < 8; t++) split_bf16(vs[t], hb.b[t], lb.b[t]);
    *reinterpret_cast<uint4*>(g_a0h + i8) = hb.u;
    *reinterpret_cast<uint4*>(g_a0l + i8) = lb.u;
}
__global__ void k_conv_w1(const float* __restrict__ W1) {
    int i = blockIdx.x * blockDim.x + threadIdx.x;
    if (i < FF0 * FF1) split_bf16(W1[i], g_w1h[i], g_w1l[i]);
}
__global__ void k_conv_w2(const float* __restrict__ W2) {
    int i = blockIdx.x * blockDim.x + threadIdx.x;
    if (i < FF1 * FF2) split_bf16(W2[i], g_w2h[i], g_w2l[i]);
}

// ---------------------------------------------------------------------------
// Normalization / graph kernels
// ---------------------------------------------------------------------------
__global__ void k_detect(const long long* __restrict__ ei) {
    if (threadIdx.x == 0 && blockIdx.x == 0) {
        int is64 = 1;
        for (int i = 0; i < 64; i++) {
            unsigned long long v = (unsigned long long)ei[i];
            if (v >= (unsigned long long)NNODES) { is64 = 0; break; }
        }
        g_is64 = is64;
    }
}
__global__ void k_deg_init() {
    int i = blockIdx.x * blockDim.x + threadIdx.x;
    if (i < NNODES) g_deg[i] = 1.0f;
}
__global__ void k_deg_edges(const void* __restrict__ eiv, const float* __restrict__ ew) {
    int e = blockIdx.x * blockDim.x + threadIdx.x;
    if (e < NEDGES) {
        int r, c;
        if (g_is64) {
            const long long* ei = (const long long*)eiv;
            r = (int)ei[e]; c = (int)ei[NEDGES + e];
        } else {
            const int* ei = (const int*)eiv;
            r = ei[e]; c = ei[NEDGES + e];
        }
        r = min(max(r, 0), NNODES - 1);
        c = min(max(c, 0), NNODES - 1);
        g_row[e] = r; g_col[e] = c;
        atomicAdd(&g_deg[c], ew[e]);
    }
}
__global__ void k_dinv() {
    int i = blockIdx.x * blockDim.x + threadIdx.x;
    if (i < NNODES) g_dinv[i] = rsqrtf(g_deg[i]);
}
__global__ void k_edge_w(const float* __restrict__ ew) {
    int e = blockIdx.x * blockDim.x + threadIdx.x;
    if (e < NEDGES) g_w[e] = g_dinv[g_row[e]] * ew[e] * g_dinv[g_col[e]];
}

template <int F4, bool HAS_BIAS, int SRC, int DST>
__global__ void k_agg_init(const float* src_arg, const float* __restrict__ bias,
                           float* dst_arg) {
    const float4* src = reinterpret_cast<const float4*>(pickc<SRC>(src_arg));
    float4*       dst = reinterpret_cast<float4*>(pick<DST>(dst_arg));
    size_t idx = (size_t)blockIdx.x * blockDim.x + threadIdx.x;
    if (idx >= (size_t)NNODES * F4) return;
    int node = (int)(idx / F4);
    int f4   = (int)(idx % F4);
    float di = g_dinv[node];
    float s  = di * di;
    float4 v = src[idx];
    float4 o;
    if (HAS_BIAS) {
        float4 b = reinterpret_cast<const float4*>(bias)[f4];
        o.x = b.x + s * v.x; o.y = b.y + s * v.y;
        o.z = b.z + s * v.z; o.w = b.w + s * v.w;
    } else {
        o.x = s * v.x; o.y = s * v.y; o.z = s * v.z; o.w = s * v.w;
    }
    dst[idx] = o;
}

template <int TPE, int SRC, int DST>
__global__ void k_scatter(const float* src_arg, float* dst_arg) {
    const float* src = pickc<SRC>(src_arg);
    float*       dst = pick<DST>(dst_arg);
    long long tid = (long long)blockIdx.x * blockDim.x + threadIdx.x;
    int e = (int)(tid / TPE);
    if (e >= NEDGES) return;
    int f = (int)(tid % TPE);
    int r = g_row[e];
    int c = g_col[e];
    float w = g_w[e];
    float4 v = reinterpret_cast<const float4*>(src)[(size_t)r * TPE + f];
    float* d = dst + ((size_t)c * TPE + f) * 4;
    atomicAdd(d + 0, w * v.x);
    atomicAdd(d + 1, w * v.y);
    atomicAdd(d + 2, w * v.z);
    atomicAdd(d + 3, w * v.w);
}

// SIMT GEMM (layer 3 only: 50000x64x256 with relu'd A)
template <int BM, int BN, int BK, int TM, int TN, int EPI, bool RELU_A,
          int SELA, int SELC>
__global__ __launch_bounds__((BM / TM) * (BN / TN))
void k_gemm(const float* __restrict__ B, const float* __restrict__ bias,
            long long aOff, long long cOff, int M, int N, int K) {
    const float* A = pickc<SELA>(nullptr) + aOff;
    float*       C = pick<SELC>(nullptr) + cOff;
    constexpr int THREADS = (BM / TM) * (BN / TN);
    __shared__ float As[BK][BM];
    __shared__ float Bs[BK][BN];
    const int tid = threadIdx.x;
    const int bm  = blockIdx.y * BM;
    const int bn  = blockIdx.x * BN;
    const int tx  = tid % (BN / TN);
    const int ty  = tid / (BN / TN);
    float acc[TM][TN];
    #pragma unroll
    for (int i = 0; i < TM; i++)
        #pragma unroll
        for (int j = 0; j < TN; j++) acc[i][j] = 0.0f;
    for (int k0 = 0; k0 < K; k0 += BK) {
        for (int i = tid * 4; i < BM * BK; i += THREADS * 4) {
            int r = i / BK, cc = i % BK, gr = bm + r;
            float4 v = make_float4(0.f, 0.f, 0.f, 0.f);
            if (gr < M)
                v = *reinterpret_cast<const float4*>(A + (size_t)gr * K + (k0 + cc));
            if (RELU_A) {
                v.x = fmaxf(v.x, 0.f); v.y = fmaxf(v.y, 0.f);
                v.z = fmaxf(v.z, 0.f); v.w = fmaxf(v.w, 0.f);
            }
            As[cc + 0][r] = v.x; As[cc + 1][r] = v.y;
            As[cc + 2][r] = v.z; As[cc + 3][r] = v.w;
        }
        for (int i = tid * 4; i < BK * BN; i += THREADS * 4) {
            int r = i / BN, cc = i % BN;
            *reinterpret_cast<float4*>(&Bs[r][cc]) =
                *reinterpret_cast<const float4*>(B + (size_t)(k0 + r) * N + bn + cc);
        }
        __syncthreads();
        #pragma unroll
        for (int k = 0; k < BK; k++) {
            float ra[TM], rb[TN];
            #pragma unroll
            for (int i = 0; i < TM; i++) ra[i] = As[k][ty * TM + i];
            #pragma unroll
            for (int j = 0; j < TN; j++) rb[j] = Bs[k][tx * TN + j];
            #pragma unroll
            for (int i = 0; i < TM; i++)
                #pragma unroll
                for (int j = 0; j < TN; j++)
                    acc[i][j] += ra[i] * rb[j];
        }
        __syncthreads();
    }
    #pragma unroll
    for (int i = 0; i < TM; i++) {
        int gm = bm + ty * TM + i;
        if (gm >= M) continue;
        #pragma unroll
        for (int j = 0; j < TN; j++) {
            int gn = bn + tx * TN + j;
            float v = acc[i][j];
            if (EPI == 1) {
                v += bias[gn];
                v = (v > 0.f) ? v : 0.01f * v;
            }
            C[(size_t)gm * N + gn] = v;
        }
    }
}

__global__ void k_finalize(float* __restrict__ out) {
    int i = blockIdx.x * blockDim.x + threadIdx.x;
    const int n4 = NNODES * FF3 / 4;
    if (i < n4) {
        float4 v = reinterpret_cast<const float4*>(g_oacc)[i];
        float4 o;
        o.x = fmaxf(v.x, 0.f); o.y = fmaxf(v.y, 0.f);
        o.z = fmaxf(v.z, 0.f); o.w = fmaxf(v.w, 0.f);
        reinterpret_cast<float4*>(out)[i] = o;
    }
}

// ---------------------------------------------------------------------------
extern "C" void kernel_launch(void* const* d_in, const int* in_sizes, int n_in,
                              void* d_out, int out_size) {
    const float* x  = nullptr;
    const void*  ei = nullptr;
    const float* ew = nullptr;
    const float* W1 = nullptr; const float* b1 = nullptr;
    const float* W2 = nullptr; const float* b2 = nullptr;
    const float* W3 = nullptr; const float* b3 = nullptr;
    for (int i = 0; i < n_in; i++) {
        const void* p = d_in[i];
        switch (in_sizes[i]) {
            case NNODES * FF0: x  = (const float*)p; break;
            case 2 * NEDGES:   ei = p;               break;
            case NEDGES:       ew = (const float*)p; break;
            case FF0 * FF1:    W1 = (const float*)p; break;
            case FF1:          b1 = (const float*)p; break;
            case FF1 * FF2:    W2 = (const float*)p; break;
            case FF2:          b2 = (const float*)p; break;
            case FF2 * FF3:    W3 = (const float*)p; break;
            case FF3:          b3 = (const float*)p; break;
            default: break;
        }
    }
    if (!x)  x  = (const float*)d_in[0];
    if (!ei) ei = d_in[1];
    if (!ew) ew = (const float*)d_in[2];
    if (!W1) W1 = (const float*)d_in[3];
    if (!b1) b1 = (const float*)d_in[4];
    if (!W2) W2 = (const float*)d_in[5];
    if (!b2) b2 = (const float*)d_in[6];
    if (!W3) W3 = (const float*)d_in[7];
    if (!b3) b3 = (const float*)d_in[8];
    float* out = (float*)d_out;

    const int TB = 256;

    k_detect   <<<1, 32>>>((const long long*)ei);
    k_deg_init <<<ceil_div_i(NNODES, TB), TB>>>();
    k_deg_edges<<<ceil_div_i(NEDGES, TB), TB>>>(ei, ew);
    k_dinv     <<<ceil_div_i(NNODES, TB), TB>>>();
    k_edge_w   <<<ceil_div_i(NEDGES, TB), TB>>>(ew);

    // weight splits (native layout)
    k_conv_w1<<<ceil_div_i(FF0 * FF1, TB), TB>>>(W1);
    k_conv_w2<<<ceil_div_i(FF1 * FF2, TB), TB>>>(W2);

    // ---- L1 aggregation: agg0 = A_norm @ X, then split to bf16 hi/lo ----
    {
        long long tot = (long long)NNODES * (FF0 / 4);
        k_agg_init<FF0 / 4, false, SEL_ARG, SEL_AGG0><<<ceil_div_i(tot, TB), TB>>>(
            x, nullptr, nullptr);
        k_scatter<FF0 / 4, SEL_ARG, SEL_AGG0>
            <<<ceil_div_i((long long)NEDGES * (FF0 / 4), TB), TB>>>(x, nullptr);
        k_conv_a<<<ceil_div_i((long long)NNODES * FF0 / 8, TB), TB>>>();
    }

    // ---- tensor GEMM1: H1 = leaky_relu(agg0 @ W1 + b1)  [bf16 hi/lo out] ----
    {
        dim3 g(FF1 / 128, ceil_div_i(NNODES, 128));   // (16, 391)
        mma_gemm<1><<<g, 256>>>(b1);
    }
    // ---- tensor GEMM2: t2 = H1 @ W2 ----
    {
        dim3 g(FF2 / 128, ceil_div_i(NNODES, 128));   // (2, 391)
        mma_gemm<2><<<g, 256>>>(nullptr);
    }

    // ---- L2 aggregation: h2 = b2 + A_norm @ t2 ----
    {
        long long tot = (long long)NNODES * (FF2 / 4);
        k_agg_init<FF2 / 4, true, SEL_T2, SEL_H2><<<ceil_div_i(tot, TB), TB>>>(
            nullptr, b2, nullptr);
        k_scatter<FF2 / 4, SEL_T2, SEL_H2>
            <<<ceil_div_i((long long)NEDGES * (FF2 / 4), TB), TB>>>(nullptr, nullptr);
    }

    // ---- L3: t3 = relu(h2) @ W3 ; oacc = b3 + A_norm @ t3 ; out = relu(oacc)
    {
        dim3 g3(FF3 / 64, ceil_div_i(NNODES, 128));
        k_gemm<128, 64, 16, 8, 4, 0, true, SEL_H2, SEL_T3><<<g3, 256>>>(
            W3, nullptr, 0, 0, NNODES, FF3, FF2);
        long long tot = (long long)NNODES * (FF3 / 4);
        k_agg_init<FF3 / 4, true, SEL_T3, SEL_OACC><<<ceil_div_i(tot, TB), TB>>>(
            nullptr, b3, nullptr);
        k_scatter<FF3 / 4, SEL_T3, SEL_OACC>
            <<<ceil_div_i((long long)NEDGES * (FF3 / 4), TB), TB>>>(nullptr, nullptr);
        k_finalize<<<ceil_div_i(NNODES * FF3 / 4, TB), TB>>>(out);
    }
}